// round 9
// baseline (speedup 1.0000x reference)
#include <cuda_runtime.h>
#include <cstdint>

// GRU-D diagonal recurrence. One thread = one (b,f) chain, T=512 steps.
// R9: cp.async (LDGSTS) -> shared-memory 4-stage ring. Loads decoupled from
// the register file; depth-3 prefetch lead. Consumer syncs via wait_group
// (same-thread visibility), reads via conflict-free LDS.

#define TT 512
#define BB 256
#define FF 256
#define BF (BB * FF)
#define UNROLL 8
#define NBATCH (TT / UNROLL)   // 64
#define BLK 64
#define STAGES 4

__device__ __forceinline__ float tanh_approx(float v) {
    float r;
    asm("tanh.approx.f32 %0, %1;" : "=f"(r) : "f"(v));
    return r;
}
__device__ __forceinline__ float ex2_f(float v) {
    float r;
    asm("ex2.approx.f32 %0, %1;" : "=f"(r) : "f"(v));
    return r;
}
__device__ __forceinline__ void cp_async4(uint32_t saddr, const float* gptr) {
    asm volatile("cp.async.ca.shared.global [%0], [%1], 4;"
                 :: "r"(saddr), "l"(gptr));
}
__device__ __forceinline__ void cp_commit() {
    asm volatile("cp.async.commit_group;" ::: "memory");
}
template <int N>
__device__ __forceinline__ void cp_wait() {
    asm volatile("cp.async.wait_group %0;" :: "n"(N) : "memory");
}

__global__ void __launch_bounds__(BLK) grud_kernel(
    const float* __restrict__ X,
    const float* __restrict__ Mask,
    const float* __restrict__ Delta,
    const float* __restrict__ x_mean,
    const float* __restrict__ w_dg_x, const float* __restrict__ b_dg_x,
    const float* __restrict__ w_dg_h, const float* __restrict__ b_dg_h,
    const float* __restrict__ w_xz,  const float* __restrict__ u_hz, const float* __restrict__ b_z,
    const float* __restrict__ w_xr,  const float* __restrict__ u_hr, const float* __restrict__ b_r,
    const float* __restrict__ w_xh,  const float* __restrict__ u_hh,
    const float* __restrict__ v_mh,  const float* __restrict__ b_h,
    float* __restrict__ out,        // [B, T, F]
    float* __restrict__ out_last)   // [B, F] or nullptr
{
    // smem ring: [stage][3 arrays][UNROLL][BLK]
    __shared__ float sm[STAGES][3][UNROLL][BLK];

    const int tx  = threadIdx.x;
    const int tid = blockIdx.x * BLK + tx;
    const int f = tid & (FF - 1);
    const int b = tid >> 8;

    const float LOG2E = 1.4426950408889634f;

    const float xm    = x_mean[f];
    const float nwdgx = -LOG2E * w_dg_x[f], nbdgx = -LOG2E * b_dg_x[f];
    const float nwdgh = -LOG2E * w_dg_h[f], nbdgh = -LOG2E * b_dg_h[f];
    const float wxz2  = 0.5f * w_xz[f], uhz2 = 0.5f * u_hz[f], bz2 = 0.5f * b_z[f];
    const float wxr2  = 0.5f * w_xr[f], uhr2 = 0.5f * u_hr[f], br2 = 0.5f * b_r[f];
    const float wxh   = w_xh[f], uhh = u_hh[f];
    const float vmh   = v_mh[f], bh  = b_h[f];

    const float* xp = X     + (size_t)b * FF + f;       // [T,B,F]: t-stride BF
    const float* mp = Mask  + (size_t)b * FF + f;
    const float* dp = Delta + (size_t)b * FF + f;
    float*       op = out   + (size_t)b * TT * FF + f;  // [B,T,F]: t-stride FF

    // Shared base addresses for this thread's column (u32 shared-space).
    uint32_t sx = (uint32_t)__cvta_generic_to_shared(&sm[0][0][0][tx]);
    uint32_t smm = (uint32_t)__cvta_generic_to_shared(&sm[0][1][0][tx]);
    uint32_t sd = (uint32_t)__cvta_generic_to_shared(&sm[0][2][0][tx]);
    const uint32_t STAGE_B = 3 * UNROLL * BLK * 4;   // bytes per stage
    const uint32_t ROW_B   = BLK * 4;                // bytes per u-row

    float h = 0.0f;

    // Issue one batch's 24 cp.asyncs into stage s (compile-time s in callers).
    auto issue_batch = [&](int n, int s) {
        const float* xq = xp + (size_t)n * (BF * UNROLL);
        const float* mq = mp + (size_t)n * (BF * UNROLL);
        const float* dq = dp + (size_t)n * (BF * UNROLL);
        const uint32_t base = (uint32_t)s * STAGE_B;
        #pragma unroll
        for (int u = 0; u < UNROLL; ++u) {
            cp_async4(sx  + base + u * ROW_B, xq + u * BF);
            cp_async4(smm + base + u * ROW_B, mq + u * BF);
            cp_async4(sd  + base + u * ROW_B, dq + u * BF);
        }
        cp_commit();
    };

    auto compute_batch = [&](int n, int s) {
        float* oq = op + (size_t)n * (FF * UNROLL);
        #pragma unroll
        for (int u = 0; u < UNROLL; ++u) {
            float x = sm[s][0][u][tx];
            float m = sm[s][1][u][tx];
            float d = sm[s][2][u][tx];

            // gamma = exp(-relu(w*d+b)) = ex2(min(0, fma(nw, d, nb)))
            float gx = ex2_f(fminf(0.0f, fmaf(nwdgx, d, nbdgx)));
            float gh = ex2_f(fminf(0.0f, fmaf(nwdgh, d, nbdgh)));

            // x' = x + (1-m)*(xi - x),  xi = xm + gx*(x - xm)
            float xi = fmaf(gx, x - xm, xm);
            x = fmaf(1.0f - m, xi - x, x);

            float pz = fmaf(wxz2, x, bz2);
            float pr = fmaf(wxr2, x, br2);
            float ph = fmaf(wxh, x, fmaf(vmh, m, bh));

            h = gh * h;

            float z  = fmaf(0.5f, tanh_approx(fmaf(uhz2, h, pz)), 0.5f);
            float r  = fmaf(0.5f, tanh_approx(fmaf(uhr2, h, pr)), 0.5f);
            float ht = tanh_approx(fmaf(uhh, r * h, ph));

            h = fmaf(z, ht - h, h);

            __stcs(oq + u * FF, h);
        }
    };

    // Prologue: batches 0..2 in flight (groups 0..2).
    issue_batch(0, 0);
    issue_batch(1, 1);
    issue_batch(2, 2);

    // Main loop: batches 0..59, unrolled x4 so stage ids are literals.
    // Iteration m: issue m+3 (group m+3), wait_group 3 (=> group m done),
    // compute m from stage m%4.
    #pragma unroll 1
    for (int n = 0; n <= NBATCH - 8; n += 4) {   // n = 0,4,...,56
        issue_batch(n + 3, 3); cp_wait<3>(); compute_batch(n,     0);
        issue_batch(n + 4, 0); cp_wait<3>(); compute_batch(n + 1, 1);
        issue_batch(n + 5, 1); cp_wait<3>(); compute_batch(n + 2, 2);
        issue_batch(n + 6, 2); cp_wait<3>(); compute_batch(n + 3, 3);
    }
    // Tail: batches 60..63. Batch 63 is the last issue (group 63).
    issue_batch(63, 3);
    cp_wait<3>(); compute_batch(60, 0);
    cp_wait<2>(); compute_batch(61, 1);
    cp_wait<1>(); compute_batch(62, 2);
    cp_wait<0>(); compute_batch(63, 3);

    if (out_last != nullptr) {
        out_last[(size_t)b * FF + f] = h;
    }
}

extern "C" void kernel_launch(void* const* d_in, const int* in_sizes, int n_in,
                              void* d_out, int out_size) {
    const float* X      = (const float*)d_in[0];
    const float* Mask   = (const float*)d_in[1];
    const float* Delta  = (const float*)d_in[2];
    const float* x_mean = (const float*)d_in[3];
    const float* w_dg_x = (const float*)d_in[4];
    const float* b_dg_x = (const float*)d_in[5];
    const float* w_dg_h = (const float*)d_in[6];
    const float* b_dg_h = (const float*)d_in[7];
    const float* w_xz   = (const float*)d_in[8];
    const float* u_hz   = (const float*)d_in[9];
    const float* b_z    = (const float*)d_in[10];
    const float* w_xr   = (const float*)d_in[11];
    const float* u_hr   = (const float*)d_in[12];
    const float* b_r    = (const float*)d_in[13];
    const float* w_xh   = (const float*)d_in[14];
    const float* u_hh   = (const float*)d_in[15];
    const float* v_mh   = (const float*)d_in[16];
    const float* b_h    = (const float*)d_in[17];

    float* out = (float*)d_out;
    const long long hs_elems = (long long)BB * TT * FF;
    float* out_last = ((long long)out_size >= hs_elems + (long long)BB * FF)
                          ? out + hs_elems : nullptr;

    grud_kernel<<<BF / BLK, BLK>>>(X, Mask, Delta, x_mean,
                                   w_dg_x, b_dg_x, w_dg_h, b_dg_h,
                                   w_xz, u_hz, b_z,
                                   w_xr, u_hr, b_r,
                                   w_xh, u_hh, v_mh, b_h,
                                   out, out_last);
}

// round 10
// speedup vs baseline: 1.4862x; 1.4862x over previous
#include <cuda_runtime.h>
#include <cstdint>

// GRU-D diagonal recurrence. One thread = one (b,f) chain, T=512 steps.
// R10: depth-3 register pipeline (4 slots, period-4 rotation, x4-unrolled
// branch-free loop). Otherwise identical to the 91.9us R5/R7 kernel.

#define TT 512
#define BB 256
#define FF 256
#define BF (BB * FF)
#define UNROLL 8
#define NBATCH (TT / UNROLL)   // 64
#define BLK 64

__device__ __forceinline__ float tanh_approx(float v) {
    float r;
    asm("tanh.approx.f32 %0, %1;" : "=f"(r) : "f"(v));
    return r;
}
__device__ __forceinline__ float ex2_f(float v) {
    float r;
    asm("ex2.approx.f32 %0, %1;" : "=f"(r) : "f"(v));
    return r;
}

__global__ void __launch_bounds__(BLK) grud_kernel(
    const float* __restrict__ X,
    const float* __restrict__ Mask,
    const float* __restrict__ Delta,
    const float* __restrict__ x_mean,
    const float* __restrict__ w_dg_x, const float* __restrict__ b_dg_x,
    const float* __restrict__ w_dg_h, const float* __restrict__ b_dg_h,
    const float* __restrict__ w_xz,  const float* __restrict__ u_hz, const float* __restrict__ b_z,
    const float* __restrict__ w_xr,  const float* __restrict__ u_hr, const float* __restrict__ b_r,
    const float* __restrict__ w_xh,  const float* __restrict__ u_hh,
    const float* __restrict__ v_mh,  const float* __restrict__ b_h,
    float* __restrict__ out,        // [B, T, F]
    float* __restrict__ out_last)   // [B, F] or nullptr
{
    const int tid = blockIdx.x * BLK + threadIdx.x;
    const int f = tid & (FF - 1);
    const int b = tid >> 8;

    const float LOG2E = 1.4426950408889634f;

    const float xm    = x_mean[f];
    const float nwdgx = -LOG2E * w_dg_x[f], nbdgx = -LOG2E * b_dg_x[f];
    const float nwdgh = -LOG2E * w_dg_h[f], nbdgh = -LOG2E * b_dg_h[f];
    const float wxz2  = 0.5f * w_xz[f], uhz2 = 0.5f * u_hz[f], bz2 = 0.5f * b_z[f];
    const float wxr2  = 0.5f * w_xr[f], uhr2 = 0.5f * u_hr[f], br2 = 0.5f * b_r[f];
    const float wxh   = w_xh[f], uhh = u_hh[f];
    const float vmh   = v_mh[f], bh  = b_h[f];

    const float* xp = X     + (size_t)b * FF + f;       // [T,B,F]: t-stride BF
    const float* mp = Mask  + (size_t)b * FF + f;
    const float* dp = Delta + (size_t)b * FF + f;
    float*       op = out   + (size_t)b * TT * FF + f;  // [B,T,F]: t-stride FF

    float h = 0.0f;

    // 4 register buffers; all slot indices below are literal constants.
    float xv[4][UNROLL], mv[4][UNROLL], dv[4][UNROLL];

    auto load_batch = [&](int n, int s) {
        const float* xq = xp + (size_t)n * (BF * UNROLL);
        const float* mq = mp + (size_t)n * (BF * UNROLL);
        const float* dq = dp + (size_t)n * (BF * UNROLL);
        #pragma unroll
        for (int u = 0; u < UNROLL; ++u) {
            xv[s][u] = __ldcs(xq + u * BF);
            mv[s][u] = __ldcs(mq + u * BF);
            dv[s][u] = __ldcs(dq + u * BF);
        }
    };
    auto compute_batch = [&](int n, int s) {
        float* oq = op + (size_t)n * (FF * UNROLL);
        #pragma unroll
        for (int u = 0; u < UNROLL; ++u) {
            float x = xv[s][u], m = mv[s][u], d = dv[s][u];

            // gamma = exp(-relu(w*d+b)) = ex2(min(0, fma(nw, d, nb)))
            float gx = ex2_f(fminf(0.0f, fmaf(nwdgx, d, nbdgx)));
            float gh = ex2_f(fminf(0.0f, fmaf(nwdgh, d, nbdgh)));

            // x' = x + (1-m)*(xi - x),  xi = xm + gx*(x - xm)
            float xi = fmaf(gx, x - xm, xm);
            x = fmaf(1.0f - m, xi - x, x);

            float pz = fmaf(wxz2, x, bz2);
            float pr = fmaf(wxr2, x, br2);
            float ph = fmaf(wxh, x, fmaf(vmh, m, bh));

            h = gh * h;

            float z  = fmaf(0.5f, tanh_approx(fmaf(uhz2, h, pz)), 0.5f);
            float r  = fmaf(0.5f, tanh_approx(fmaf(uhr2, h, pr)), 0.5f);
            float ht = tanh_approx(fmaf(uhh, r * h, ph));

            h = fmaf(z, ht - h, h);

            __stcs(oq + u * FF, h);
        }
    };

    // Depth-3 pipeline: batches 0..2 in flight before any compute.
    load_batch(0, 0);
    load_batch(1, 1);
    load_batch(2, 2);

    // Branch-free main loop: n = 0,4,...,56 (computes 0..59, loads thru 62).
    #pragma unroll 1
    for (int n = 0; n <= NBATCH - 8; n += 4) {
        load_batch(n + 3, 3);  compute_batch(n,     0);
        load_batch(n + 4, 0);  compute_batch(n + 1, 1);
        load_batch(n + 5, 1);  compute_batch(n + 2, 2);
        load_batch(n + 6, 2);  compute_batch(n + 3, 3);
    }
    // Slots now: 60->s0, 61->s1, 62->s2.
    load_batch(63, 3);
    compute_batch(60, 0);
    compute_batch(61, 1);
    compute_batch(62, 2);
    compute_batch(63, 3);

    if (out_last != nullptr) {
        out_last[(size_t)b * FF + f] = h;
    }
}

extern "C" void kernel_launch(void* const* d_in, const int* in_sizes, int n_in,
                              void* d_out, int out_size) {
    const float* X      = (const float*)d_in[0];
    const float* Mask   = (const float*)d_in[1];
    const float* Delta  = (const float*)d_in[2];
    const float* x_mean = (const float*)d_in[3];
    const float* w_dg_x = (const float*)d_in[4];
    const float* b_dg_x = (const float*)d_in[5];
    const float* w_dg_h = (const float*)d_in[6];
    const float* b_dg_h = (const float*)d_in[7];
    const float* w_xz   = (const float*)d_in[8];
    const float* u_hz   = (const float*)d_in[9];
    const float* b_z    = (const float*)d_in[10];
    const float* w_xr   = (const float*)d_in[11];
    const float* u_hr   = (const float*)d_in[12];
    const float* b_r    = (const float*)d_in[13];
    const float* w_xh   = (const float*)d_in[14];
    const float* u_hh   = (const float*)d_in[15];
    const float* v_mh   = (const float*)d_in[16];
    const float* b_h    = (const float*)d_in[17];

    float* out = (float*)d_out;
    const long long hs_elems = (long long)BB * TT * FF;
    float* out_last = ((long long)out_size >= hs_elems + (long long)BB * FF)
                          ? out + hs_elems : nullptr;

    grud_kernel<<<BF / BLK, BLK>>>(X, Mask, Delta, x_mean,
                                   w_dg_x, b_dg_x, w_dg_h, b_dg_h,
                                   w_xz, u_hz, b_z,
                                   w_xr, u_hr, b_r,
                                   w_xh, u_hh, v_mh, b_h,
                                   out, out_last);
}